// round 12
// baseline (speedup 1.0000x reference)
#include <cuda_runtime.h>
#include <cuda_pipeline.h>
#include <cstdint>

// Fused YOLO decode, single launch, double-buffered cp.async tiles.
//
// Each block processes TWO 169-cell tiles with a 2-stage pipeline:
//   issue cp.async(tile A -> buf0); commit
//   issue cp.async(tile B -> buf1); commit
//   wait_prior(1); sync; decode A (direct stores)
//   wait_prior(0); sync; decode B
// Copy latency of A hides behind B's issue; B's behind A's decode.
// Tile copy: 16B LDGSTS of the aligned superset [t0-m, t0-m+172) per
// channel row (m = t0 mod 4); smem channel-major pitch 172.
// Decode: thread t -> row t (507 rows), 3 STG.64 + mask float per row.
// Output: boxes [N,6] in scale order 13,26,52, then mask [N].

#define TPB 512
#define TILE 169
#define NCH 45
#define TROWS (TILE * 3)        // 507

#define PITCH_V 172             // 43 float4 per channel row
#define NF4_V  (NCH * 43)       // 1935
#define NF4_13 1902             // (45*169 + 3)/4

#define BUF_FLOATS (NCH * PITCH_V)        // 7740
#define SMEM_BYTES (2 * BUF_FLOATS * 4)   // 61,920

#define B52 1024   // blocks (2 tiles each): 2048 tiles
#define B26 256    // 512 tiles
#define B13 64     // 128 tiles (1 image per tile)

#define ROWS13 64896
#define ROWS26 259584
#define ROWS52 1038336
#define ROWBASE13 0
#define ROWBASE26 ROWS13
#define ROWBASE52 (ROWS13 + ROWS26)

// ---- decode 507 rows from channel-major smem (pitch PITCH), direct store
template<int W, int STRIDE, int PITCH>
__device__ __forceinline__ void decode_tile(const float* __restrict__ s,
                                            int m,
                                            const float* __restrict__ anchors,
                                            float thr,
                                            float* __restrict__ boxes,
                                            float* __restrict__ mask,
                                            size_t orow0, int t0, int t)
{
    if (t >= TROWS) return;

    const int lc = t / 3;
    const int a  = t - 3 * lc;

    const float* sc = s + (a * 15) * PITCH + m + lc;

    const float o0 = sc[0 * PITCH];
    const float o1 = sc[1 * PITCH];
    const float o2 = sc[2 * PITCH];
    const float o3 = sc[3 * PITCH];
    const float o4 = sc[4 * PITCH];

    float best = sc[5 * PITCH];
    int bi = 0;
    #pragma unroll
    for (int c = 1; c < 10; ++c) {
        const float q = sc[(5 + c) * PITCH];
        if (q > best) { best = q; bi = c; }
    }

    const int cw = t0 + lc;
    const int h  = cw / W;                 // compile-time W
    const int w  = cw - h * W;

    const float px = ((float)w + o1) * (float)STRIDE;
    const float py = ((float)h + o2) * (float)STRIDE;
    const float pw = __ldg(anchors + 2 * a + 0) * __expf(o3);
    const float ph = __ldg(anchors + 2 * a + 1) * __expf(o4);

    const size_t orow = orow0 + t;
    float2* ob = (float2*)(boxes + orow * 6);
    ob[0] = make_float2(o0,              px - 0.5f * pw);
    ob[1] = make_float2(py - 0.5f * ph,  px + 0.5f * pw);
    ob[2] = make_float2(py + 0.5f * ph,  (float)bi);

    mask[orow] = (o0 > thr) ? 1.0f : 0.0f;
}

// ---- issue 16B cp.async copy of one strided-row tile into buf ----
template<int W>
__device__ __forceinline__ void issue_copy(float4* __restrict__ buf4,
                                           const float* __restrict__ in,
                                           int b, int t0, int m, int t)
{
    constexpr int HW  = W * W;
    constexpr int HW4 = HW / 4;
    const float4* src4 = (const float4*)(in)
                       + ((size_t)b * NCH * HW + t0 - m) / 4;
    #pragma unroll
    for (int k = 0; k < 4; ++k) {
        const int r = t + k * TPB;
        if (k == 3 && r >= NF4_V) break;
        const int c = r / 43;
        const int q = r - c * 43;
        __pipeline_memcpy_async(&buf4[c * 43 + q], src4 + c * HW4 + q, 16);
    }
    __pipeline_commit();
}

template<int W, int TILES_PER_B, int STRIDE>
__device__ __forceinline__ void two_tile_path(const float* __restrict__ in,
                                              const float* __restrict__ anchors,
                                              float thr,
                                              float* __restrict__ boxes,
                                              float* __restrict__ mask,
                                              size_t rowbase,
                                              int blk, int t,
                                              float* __restrict__ s0,
                                              float* __restrict__ s1)
{
    constexpr int HW = W * W;

    const int T0 = blk * 2, T1 = T0 + 1;
    const int b0 = T0 / TILES_PER_B, j0 = T0 - b0 * TILES_PER_B;
    const int b1 = T1 / TILES_PER_B, j1 = T1 - b1 * TILES_PER_B;
    const int t00 = j0 * TILE, m0 = t00 & 3;
    const int t01 = j1 * TILE, m1 = t01 & 3;

    issue_copy<W>((float4*)s0, in, b0, t00, m0, t);   // group 0
    issue_copy<W>((float4*)s1, in, b1, t01, m1, t);   // group 1

    __pipeline_wait_prior(1);          // group 0 complete
    __syncthreads();
    decode_tile<W, STRIDE, PITCH_V>(s0, m0, anchors, thr, boxes, mask,
                                    rowbase + ((size_t)b0 * HW + t00) * 3,
                                    t00, t);

    __pipeline_wait_prior(0);          // group 1 complete
    __syncthreads();
    decode_tile<W, STRIDE, PITCH_V>(s1, m1, anchors, thr, boxes, mask,
                                    rowbase + ((size_t)b1 * HW + t01) * 3,
                                    t01, t);
}

__global__ __launch_bounds__(TPB, 3)
void decode_fused_kernel(const float* __restrict__ in13,
                         const float* __restrict__ in26,
                         const float* __restrict__ in52,
                         const float* __restrict__ anc13,
                         const float* __restrict__ anc26,
                         const float* __restrict__ anc52,
                         const float* __restrict__ thresh_p,
                         float* __restrict__ boxes,
                         float* __restrict__ mask)
{
    extern __shared__ float smem[];    // 2 * 7740 floats
    float* s0 = smem;
    float* s1 = smem + BUF_FLOATS;

    const int bid = blockIdx.x;
    const int t = threadIdx.x;
    const float thr = __ldg(thresh_p);

    if (bid < B52) {
        two_tile_path<52, 16, 8>(in52, anc52, thr, boxes, mask,
                                 (size_t)ROWBASE52, bid, t, s0, s1);
    } else if (bid < B52 + B26) {
        two_tile_path<26, 4, 16>(in26, anc26, thr, boxes, mask,
                                 (size_t)ROWBASE26, bid - B52, t, s0, s1);
    } else {
        // ---- scale 13: two contiguous images, aligned superset copies ----
        const int blk = bid - (B52 + B26);
        const int b0 = blk * 2, b1 = b0 + 1;
        const int m0 = b0 & 3, m1 = b1 & 3;     // 7605 % 4 == 1

        const float4* src0 = (const float4*)(in13)
                           + ((size_t)b0 * (NCH * TILE) - m0) / 4;
        const float4* src1 = (const float4*)(in13)
                           + ((size_t)b1 * (NCH * TILE) - m1) / 4;
        float4* d0 = (float4*)s0;
        float4* d1 = (float4*)s1;

        #pragma unroll
        for (int k = 0; k < 4; ++k) {
            const int r = t + k * TPB;
            if (k == 3 && r >= NF4_13) break;
            __pipeline_memcpy_async(&d0[r], src0 + r, 16);
        }
        __pipeline_commit();
        #pragma unroll
        for (int k = 0; k < 4; ++k) {
            const int r = t + k * TPB;
            if (k == 3 && r >= NF4_13) break;
            __pipeline_memcpy_async(&d1[r], src1 + r, 16);
        }
        __pipeline_commit();

        __pipeline_wait_prior(1);
        __syncthreads();
        decode_tile<13, 32, TILE>(s0, m0, anc13, thr, boxes, mask,
                                  (size_t)ROWBASE13 + (size_t)b0 * TROWS, 0, t);

        __pipeline_wait_prior(0);
        __syncthreads();
        decode_tile<13, 32, TILE>(s1, m1, anc13, thr, boxes, mask,
                                  (size_t)ROWBASE13 + (size_t)b1 * TROWS, 0, t);
    }
}

extern "C" void kernel_launch(void* const* d_in, const int* in_sizes, int n_in,
                              void* d_out, int out_size)
{
    const float* out13 = (const float*)d_in[0];
    const float* out26 = (const float*)d_in[1];
    const float* out52 = (const float*)d_in[2];
    const float* anc13 = (const float*)d_in[3];
    const float* anc26 = (const float*)d_in[4];
    const float* anc52 = (const float*)d_in[5];
    const float* thr   = (const float*)d_in[6];

    float* out = (float*)d_out;
    const int rowsTot = ROWS13 + ROWS26 + ROWS52;   // 1,362,816

    float* boxes = out;                       // [rowsTot, 6]
    float* mask  = out + (size_t)rowsTot * 6; // [rowsTot]

    cudaFuncSetAttribute(decode_fused_kernel,
                         cudaFuncAttributeMaxDynamicSharedMemorySize,
                         SMEM_BYTES);

    decode_fused_kernel<<<B52 + B26 + B13, TPB, SMEM_BYTES>>>(
        out13, out26, out52, anc13, anc26, anc52, thr, boxes, mask);
}

// round 13
// speedup vs baseline: 1.0609x; 1.0609x over previous
#include <cuda_runtime.h>
#include <cuda_pipeline.h>
#include <cstdint>

// Fused YOLO decode, single launch, cp.async-staged, TPB=512 single pass.
//
// Each block: one 169-cell tile (13*13 divides every HW).
//   Phase 1: 16B cp.async of the aligned superset [t0-m, t0-m+172) of each
//            of the 45 channel rows -> smem (channel-major, pitch 172).
//            4 iterations/thread at TPB=512.
//   Phase 2: single-pass decode, thread t -> row t (507 rows), direct
//            stores: 3 STG.64 + 1 mask float per row.
// 512 threads x 4 CTAs/SM = 64 warps/SM (HW max) for latency overlap.
// Output: boxes [N,6] in scale order 13,26,52, then mask [N].

#define TPB 512
#define TILE 169
#define NCH 45
#define TROWS (TILE * 3)        // 507

#define PITCH_V 172             // 43 float4 per channel row
#define NF4_V  (NCH * 43)       // 1935
#define NF4_13 1902             // (45*169 + 3)/4

#define SMEM_FLOATS (NCH * PITCH_V)   // 7740 floats = 30,960 B

#define BLK13 128
#define BLK26 512
#define BLK52 2048

#define ROWS13 64896
#define ROWS26 259584
#define ROWS52 1038336
#define ROWBASE13 0
#define ROWBASE26 ROWS13
#define ROWBASE52 (ROWS13 + ROWS26)

// ---- decode 507 rows (single pass), direct stores ----
template<int W, int STRIDE, int PITCH>
__device__ __forceinline__ void decode_tile(const float* __restrict__ s,
                                            int m,
                                            const float* __restrict__ anchors,
                                            float thr,
                                            float* __restrict__ boxes,
                                            float* __restrict__ mask,
                                            size_t orow0, int t0, int t)
{
    if (t >= TROWS) return;

    const int lc = t / 3;
    const int a  = t - 3 * lc;

    const float* sc = s + (a * 15) * PITCH + m + lc;

    const float o0 = sc[0 * PITCH];
    const float o1 = sc[1 * PITCH];
    const float o2 = sc[2 * PITCH];
    const float o3 = sc[3 * PITCH];
    const float o4 = sc[4 * PITCH];

    float best = sc[5 * PITCH];
    int bi = 0;
    #pragma unroll
    for (int c = 1; c < 10; ++c) {
        const float q = sc[(5 + c) * PITCH];
        if (q > best) { best = q; bi = c; }
    }

    const int cw = t0 + lc;
    const int h  = cw / W;                 // compile-time W
    const int w  = cw - h * W;

    const float px = ((float)w + o1) * (float)STRIDE;
    const float py = ((float)h + o2) * (float)STRIDE;
    const float pw = __ldg(anchors + 2 * a + 0) * __expf(o3);
    const float ph = __ldg(anchors + 2 * a + 1) * __expf(o4);

    const size_t orow = orow0 + t;
    float2* ob = (float2*)(boxes + orow * 6);
    ob[0] = make_float2(o0,              px - 0.5f * pw);
    ob[1] = make_float2(py - 0.5f * ph,  px + 0.5f * pw);
    ob[2] = make_float2(py + 0.5f * ph,  (float)bi);

    mask[orow] = (o0 > thr) ? 1.0f : 0.0f;
}

template<int W, int TILES_PER_B, int STRIDE>
__device__ __forceinline__ void tile_path(const float* __restrict__ in,
                                          const float* __restrict__ anchors,
                                          float thr,
                                          float* __restrict__ boxes,
                                          float* __restrict__ mask,
                                          size_t rowbase,
                                          int blk, int t, float* s)
{
    constexpr int HW  = W * W;        // % 4 == 0
    constexpr int HW4 = HW / 4;
    const int b  = blk / TILES_PER_B;
    const int j  = blk - b * TILES_PER_B;
    const int t0 = j * TILE;
    const int m  = t0 & 3;

    float4* s4 = (float4*)s;
    const float4* src4 = (const float4*)(in)
                       + ((size_t)b * NCH * HW + t0 - m) / 4;

    #pragma unroll
    for (int k = 0; k < 4; ++k) {
        const int r = t + k * TPB;
        if (k == 3 && r >= NF4_V) break;
        const int c = r / 43;
        const int q = r - c * 43;
        __pipeline_memcpy_async(&s4[c * 43 + q], src4 + c * HW4 + q, 16);
    }
    __pipeline_commit();
    __pipeline_wait_prior(0);
    __syncthreads();

    const size_t orow0 = rowbase + ((size_t)b * HW + t0) * 3;
    decode_tile<W, STRIDE, PITCH_V>(s, m, anchors, thr, boxes, mask,
                                    orow0, t0, t);
}

__global__ __launch_bounds__(TPB, 4)
void decode_fused_kernel(const float* __restrict__ in13,
                         const float* __restrict__ in26,
                         const float* __restrict__ in52,
                         const float* __restrict__ anc13,
                         const float* __restrict__ anc26,
                         const float* __restrict__ anc52,
                         const float* __restrict__ thresh_p,
                         float* __restrict__ boxes,
                         float* __restrict__ mask)
{
    __shared__ alignas(16) float s[SMEM_FLOATS];   // 30,960 B

    const int bid = blockIdx.x;
    const int t = threadIdx.x;
    const float thr = __ldg(thresh_p);

    if (bid < BLK52) {
        tile_path<52, 16, 8>(in52, anc52, thr, boxes, mask,
                             (size_t)ROWBASE52, bid, t, s);
    } else if (bid < BLK52 + BLK26) {
        tile_path<26, 4, 16>(in26, anc26, thr, boxes, mask,
                             (size_t)ROWBASE26, bid - BLK52, t, s);
    } else {
        // ---- scale 13: contiguous image, aligned superset copy ----
        const int b = bid - (BLK52 + BLK26);
        const int m = b & 3;                       // 7605 % 4 == 1
        float4* s4 = (float4*)s;
        const float4* src4 = (const float4*)(in13)
                           + ((size_t)b * (NCH * TILE) - m) / 4;

        #pragma unroll
        for (int k = 0; k < 4; ++k) {
            const int r = t + k * TPB;
            if (k == 3 && r >= NF4_13) break;
            __pipeline_memcpy_async(&s4[r], src4 + r, 16);
        }
        __pipeline_commit();
        __pipeline_wait_prior(0);
        __syncthreads();

        const size_t orow0 = (size_t)ROWBASE13 + (size_t)b * TROWS;
        decode_tile<13, 32, TILE>(s, m, anc13, thr, boxes, mask, orow0, 0, t);
    }
}

extern "C" void kernel_launch(void* const* d_in, const int* in_sizes, int n_in,
                              void* d_out, int out_size)
{
    const float* out13 = (const float*)d_in[0];
    const float* out26 = (const float*)d_in[1];
    const float* out52 = (const float*)d_in[2];
    const float* anc13 = (const float*)d_in[3];
    const float* anc26 = (const float*)d_in[4];
    const float* anc52 = (const float*)d_in[5];
    const float* thr   = (const float*)d_in[6];

    float* out = (float*)d_out;
    const int rowsTot = ROWS13 + ROWS26 + ROWS52;   // 1,362,816

    float* boxes = out;                       // [rowsTot, 6]
    float* mask  = out + (size_t)rowsTot * 6; // [rowsTot]

    decode_fused_kernel<<<BLK52 + BLK26 + BLK13, TPB>>>(
        out13, out26, out52, anc13, anc26, anc52, thr, boxes, mask);
}

// round 14
// speedup vs baseline: 1.1454x; 1.0796x over previous
#include <cuda_runtime.h>
#include <cuda_pipeline.h>
#include <cstdint>

// Fused YOLO decode, single launch, cp.async-staged, small independent CTAs.
//
// TPB=128, per-scale tile sizes chosen so smem <= 19.4KB -> 11 CTAs/SM of
// independently phased copy->decode pipelines (the R10->R13 comparison showed
// independent-CTA count, not warp count, governs latency hiding here).
//   scale 52: 104-cell tile, all 45 channels, smem pitch 108 (conflict-free)
//   scale 26:  52-cell tile, all 45 channels, smem pitch 52  (conflict-free)
//   scale 13: anchor-split: one block = 15 contiguous channels of one image
// Copy = 16B cp.async (LDGSTS, structurally unserializable). Decode: thread
// -> output row, 3 STG.64 + mask float.
// Output: boxes [N,6] in scale order 13,26,52, then mask [N].

#define TPB 128
#define NCH 45

#define B52 3328    // 128 * (2704/104)
#define B26 1664    // 128 * (676/52)
#define B13 384     // 128 * 3 anchors

#define ROWS13 64896
#define ROWS26 259584
#define ROWS52 1038336
#define ROWBASE13 0
#define ROWBASE26 ROWS13
#define ROWBASE52 (ROWS13 + ROWS26)

#define SMEM_FLOATS 4860      // 45 * 108 = 19,440 B (max over paths)

// ---- generic tile path: TILEC cells, all 45 channels, pitch PITCH ----
template<int W, int TILEC, int PITCH, int STRIDE>
__device__ __forceinline__ void tile_path(const float* __restrict__ in,
                                          const float* __restrict__ anchors,
                                          float thr,
                                          float* __restrict__ boxes,
                                          float* __restrict__ mask,
                                          size_t rowbase,
                                          int blk, int t, float* s)
{
    constexpr int HW = W * W;
    constexpr int TILES_PER_B = HW / TILEC;   // TILEC % 4 == 0 -> t0 % 4 == 0
    constexpr int F4ROW  = TILEC / 4;
    constexpr int PF4ROW = PITCH / 4;
    constexpr int NF4 = NCH * F4ROW;
    constexpr int TR  = TILEC * 3;

    const int b  = blk / TILES_PER_B;
    const int j  = blk - b * TILES_PER_B;
    const int t0 = j * TILEC;

    float4* s4 = (float4*)s;
    const float4* src4 = (const float4*)in + ((size_t)b * NCH * HW + t0) / 4;

    constexpr int NCP = (NF4 + TPB - 1) / TPB;
    #pragma unroll
    for (int k = 0; k < NCP; ++k) {
        const int r = t + k * TPB;
        if ((NF4 % TPB) && k == NCP - 1 && r >= NF4) break;
        const int c = r / F4ROW;
        const int q = r - c * F4ROW;
        __pipeline_memcpy_async(&s4[c * PF4ROW + q],
                                src4 + (size_t)c * (HW / 4) + q, 16);
    }
    __pipeline_commit();
    __pipeline_wait_prior(0);
    __syncthreads();

    const size_t orow0 = rowbase + ((size_t)b * HW + t0) * 3;

    constexpr int ND = (TR + TPB - 1) / TPB;
    #pragma unroll
    for (int k = 0; k < ND; ++k) {
        const int r = t + k * TPB;
        if ((TR % TPB) && k == ND - 1 && r >= TR) break;

        const int lc = r / 3;
        const int a  = r - 3 * lc;

        const float* sc = s + (a * 15) * PITCH + lc;

        const float o0 = sc[0 * PITCH];
        const float o1 = sc[1 * PITCH];
        const float o2 = sc[2 * PITCH];
        const float o3 = sc[3 * PITCH];
        const float o4 = sc[4 * PITCH];

        float best = sc[5 * PITCH];
        int bi = 0;
        #pragma unroll
        for (int c = 1; c < 10; ++c) {
            const float q = sc[(5 + c) * PITCH];
            if (q > best) { best = q; bi = c; }
        }

        const int cw = t0 + lc;
        const int h  = cw / W;
        const int w  = cw - h * W;

        const float px = ((float)w + o1) * (float)STRIDE;
        const float py = ((float)h + o2) * (float)STRIDE;
        const float pw = __ldg(anchors + 2 * a + 0) * __expf(o3);
        const float ph = __ldg(anchors + 2 * a + 1) * __expf(o4);

        const size_t orow = orow0 + r;
        float2* ob = (float2*)(boxes + orow * 6);
        ob[0] = make_float2(o0,              px - 0.5f * pw);
        ob[1] = make_float2(py - 0.5f * ph,  px + 0.5f * pw);
        ob[2] = make_float2(py + 0.5f * ph,  (float)bi);

        mask[orow] = (o0 > thr) ? 1.0f : 0.0f;
    }
}

__global__ __launch_bounds__(TPB)
void decode_fused_kernel(const float* __restrict__ in13,
                         const float* __restrict__ in26,
                         const float* __restrict__ in52,
                         const float* __restrict__ anc13,
                         const float* __restrict__ anc26,
                         const float* __restrict__ anc52,
                         const float* __restrict__ thresh_p,
                         float* __restrict__ boxes,
                         float* __restrict__ mask)
{
    __shared__ alignas(16) float s[SMEM_FLOATS];

    const int bid = blockIdx.x;
    const int t = threadIdx.x;
    const float thr = __ldg(thresh_p);

    if (bid < B52) {
        tile_path<52, 104, 108, 8>(in52, anc52, thr, boxes, mask,
                                   (size_t)ROWBASE52, bid, t, s);
    } else if (bid < B52 + B26) {
        tile_path<26, 52, 52, 16>(in26, anc26, thr, boxes, mask,
                                  (size_t)ROWBASE26, bid - B52, t, s);
    } else {
        // ---- scale 13: anchor-split (15 contiguous channels of one image)
        const int blk = bid - (B52 + B26);      // = 3*b + a
        const int b = blk / 3;
        const int a = blk - 3 * b;

        // float offset of this anchor's 15x169 channel block: 2535*blk
        const int m = (3 * blk) & 3;            // 2535 % 4 == 3
        const size_t off = (size_t)2535 * blk;
        const float4* src4 = (const float4*)in13 + (off - m) / 4;
        const int nf4 = (m + 2535 + 3) >> 2;    // 634 or 635; end never OOB

        float4* s4 = (float4*)s;
        #pragma unroll
        for (int k = 0; k < 5; ++k) {
            const int r = t + k * TPB;
            if (k == 4 && r >= nf4) break;
            __pipeline_memcpy_async(&s4[r], src4 + r, 16);
        }
        __pipeline_commit();
        __pipeline_wait_prior(0);
        __syncthreads();

        const float aw = __ldg(anc13 + 2 * a + 0);
        const float ah = __ldg(anc13 + 2 * a + 1);

        #pragma unroll
        for (int k = 0; k < 2; ++k) {
            const int lc = t + k * TPB;
            if (k == 1 && lc >= 169) break;

            const float* sc = s + m + lc;

            const float o0 = sc[0 * 169];
            const float o1 = sc[1 * 169];
            const float o2 = sc[2 * 169];
            const float o3 = sc[3 * 169];
            const float o4 = sc[4 * 169];

            float best = sc[5 * 169];
            int bi = 0;
            #pragma unroll
            for (int c = 1; c < 10; ++c) {
                const float q = sc[(5 + c) * 169];
                if (q > best) { best = q; bi = c; }
            }

            const int h = lc / 13;
            const int w = lc - h * 13;

            const float px = ((float)w + o1) * 32.0f;
            const float py = ((float)h + o2) * 32.0f;
            const float pw = aw * __expf(o3);
            const float ph = ah * __expf(o4);

            const size_t orow = (size_t)ROWBASE13 + ((size_t)b * 169 + lc) * 3 + a;
            float2* ob = (float2*)(boxes + orow * 6);
            ob[0] = make_float2(o0,              px - 0.5f * pw);
            ob[1] = make_float2(py - 0.5f * ph,  px + 0.5f * pw);
            ob[2] = make_float2(py + 0.5f * ph,  (float)bi);

            mask[orow] = (o0 > thr) ? 1.0f : 0.0f;
        }
    }
}

extern "C" void kernel_launch(void* const* d_in, const int* in_sizes, int n_in,
                              void* d_out, int out_size)
{
    const float* out13 = (const float*)d_in[0];
    const float* out26 = (const float*)d_in[1];
    const float* out52 = (const float*)d_in[2];
    const float* anc13 = (const float*)d_in[3];
    const float* anc26 = (const float*)d_in[4];
    const float* anc52 = (const float*)d_in[5];
    const float* thr   = (const float*)d_in[6];

    float* out = (float*)d_out;
    const int rowsTot = ROWS13 + ROWS26 + ROWS52;   // 1,362,816

    float* boxes = out;                       // [rowsTot, 6]
    float* mask  = out + (size_t)rowsTot * 6; // [rowsTot]

    decode_fused_kernel<<<B52 + B26 + B13, TPB>>>(
        out13, out26, out52, anc13, anc26, anc52, thr, boxes, mask);
}

// round 15
// speedup vs baseline: 1.2462x; 1.0880x over previous
#include <cuda_runtime.h>
#include <cuda_pipeline.h>
#include <cuda.h>
#include <cstdint>

// Fused YOLO decode, single launch, TMA-staged tiles.
//
// Scales 52/26: one cp.async.bulk.tensor.2d per block loads a [45 ch x TILEC
// cells] tile into smem (box widths 104/52 cells = 416/208 B, 16B-legal;
// global row strides 10816/2704 B, 16B-legal). Decode: thread -> output row,
// 3 STG.64 + mask float (proven R10/R14 code).
// Scale 13 (global row stride 676 B, TMA-illegal): anchor-split cp.async
// path (15 contiguous channels per block), proven in R14.
// Output: boxes [N,6] in scale order 13,26,52, then mask [N].

#define TPB 128
#define NCH 45

#define T52 104
#define T26 52
#define B52T 3328   // 128 images * 26 tiles
#define B26T 1664   // 128 images * 13 tiles
#define B13  384    // 128 images * 3 anchors

#define ROWS13 64896
#define ROWS26 259584
#define ROWS52 1038336
#define ROWBASE13 0
#define ROWBASE26 ROWS13
#define ROWBASE52 (ROWS13 + ROWS26)

#define SMEM_FLOATS (NCH * T52)   // 4680 floats = 18,720 B (max path)

__device__ __forceinline__ uint32_t smem_u32(const void* p) {
    return (uint32_t)__cvta_generic_to_shared(p);
}

// ---- decode TR rows from channel-major smem tile (pitch TILEC) ----
template<int W, int TILEC, int STRIDE>
__device__ __forceinline__ void decode_rows(const float* __restrict__ s,
                                            const float* __restrict__ anchors,
                                            float thr,
                                            float* __restrict__ boxes,
                                            float* __restrict__ mask,
                                            size_t orow0, int t0, int t)
{
    constexpr int TR = TILEC * 3;
    constexpr int ND = (TR + TPB - 1) / TPB;
    #pragma unroll
    for (int k = 0; k < ND; ++k) {
        const int r = t + k * TPB;
        if ((TR % TPB) && k == ND - 1 && r >= TR) break;

        const int lc = r / 3;
        const int a  = r - 3 * lc;

        const float* sc = s + (a * 15) * TILEC + lc;

        const float o0 = sc[0 * TILEC];
        const float o1 = sc[1 * TILEC];
        const float o2 = sc[2 * TILEC];
        const float o3 = sc[3 * TILEC];
        const float o4 = sc[4 * TILEC];

        float best = sc[5 * TILEC];
        int bi = 0;
        #pragma unroll
        for (int c = 1; c < 10; ++c) {
            const float q = sc[(5 + c) * TILEC];
            if (q > best) { best = q; bi = c; }
        }

        const int cw = t0 + lc;
        const int h  = cw / W;
        const int w  = cw - h * W;

        const float px = ((float)w + o1) * (float)STRIDE;
        const float py = ((float)h + o2) * (float)STRIDE;
        const float pw = __ldg(anchors + 2 * a + 0) * __expf(o3);
        const float ph = __ldg(anchors + 2 * a + 1) * __expf(o4);

        const size_t orow = orow0 + r;
        float2* ob = (float2*)(boxes + orow * 6);
        ob[0] = make_float2(o0,              px - 0.5f * pw);
        ob[1] = make_float2(py - 0.5f * ph,  px + 0.5f * pw);
        ob[2] = make_float2(py + 0.5f * ph,  (float)bi);

        mask[orow] = (o0 > thr) ? 1.0f : 0.0f;
    }
}

// ---- TMA tile path ----
template<int W, int TILEC, int STRIDE>
__device__ __forceinline__ void tma_path(const CUtensorMap* __restrict__ map,
                                         const float* __restrict__ anchors,
                                         float thr,
                                         float* __restrict__ boxes,
                                         float* __restrict__ mask,
                                         size_t rowbase,
                                         int blk, int t,
                                         float* __restrict__ s,
                                         unsigned long long* __restrict__ mbar)
{
    constexpr int HW  = W * W;
    constexpr int TPI = HW / TILEC;           // exact
    constexpr uint32_t TBYTES = NCH * TILEC * 4;

    const int b  = blk / TPI;
    const int j  = blk - b * TPI;
    const int t0 = j * TILEC;

    const uint32_t mb = smem_u32(mbar);
    const uint32_t sa = smem_u32(s);

    if (t == 0) {
        asm volatile("mbarrier.init.shared::cta.b64 [%0], %1;"
                     :: "r"(mb), "r"(1) : "memory");
    }
    __syncthreads();

    if (t == 0) {
        asm volatile("mbarrier.arrive.expect_tx.shared::cta.b64 _, [%0], %1;"
                     :: "r"(mb), "r"(TBYTES) : "memory");
        asm volatile(
            "cp.async.bulk.tensor.2d.shared::cta.global.tile.mbarrier::complete_tx::bytes "
            "[%0], [%1, {%2, %3}], [%4];"
            :: "r"(sa), "l"(map), "r"(t0), "r"(b * NCH), "r"(mb)
            : "memory");
    }

    // wait for TMA completion, phase 0 (pattern from test_tma.cu)
    {
        uint32_t done = 0;
        while (!done) {
            asm volatile(
                "{\n\t.reg .pred p;\n\t"
                "mbarrier.try_wait.parity.shared::cta.b64 p, [%1], %2;\n\t"
                "selp.b32 %0, 1, 0, p;\n\t}"
                : "=r"(done) : "r"(mb), "r"(0) : "memory");
        }
    }

    const size_t orow0 = rowbase + ((size_t)b * HW + t0) * 3;
    decode_rows<W, TILEC, STRIDE>(s, anchors, thr, boxes, mask, orow0, t0, t);
}

__global__ __launch_bounds__(TPB)
void decode_fused_kernel(const float* __restrict__ in13,
                         const float* __restrict__ anc13,
                         const float* __restrict__ anc26,
                         const float* __restrict__ anc52,
                         const float* __restrict__ thresh_p,
                         float* __restrict__ boxes,
                         float* __restrict__ mask,
                         const __grid_constant__ CUtensorMap map26,
                         const __grid_constant__ CUtensorMap map52)
{
    __shared__ alignas(128) float s[SMEM_FLOATS];
    __shared__ alignas(8) unsigned long long mbar;

    const int bid = blockIdx.x;
    const int t = threadIdx.x;
    const float thr = __ldg(thresh_p);

    if (bid < B52T) {
        tma_path<52, T52, 8>(&map52, anc52, thr, boxes, mask,
                             (size_t)ROWBASE52, bid, t, s, &mbar);
    } else if (bid < B52T + B26T) {
        tma_path<26, T26, 16>(&map26, anc26, thr, boxes, mask,
                              (size_t)ROWBASE26, bid - B52T, t, s, &mbar);
    } else {
        // ---- scale 13: anchor-split cp.async (proven R14 path) ----
        const int blk = bid - (B52T + B26T);    // = 3*b + a
        const int b = blk / 3;
        const int a = blk - 3 * b;

        const int m = (3 * blk) & 3;            // 2535 % 4 == 3
        const size_t off = (size_t)2535 * blk;
        const float4* src4 = (const float4*)in13 + (off - m) / 4;
        const int nf4 = (m + 2535 + 3) >> 2;

        float4* s4 = (float4*)s;
        #pragma unroll
        for (int k = 0; k < 5; ++k) {
            const int r = t + k * TPB;
            if (k == 4 && r >= nf4) break;
            __pipeline_memcpy_async(&s4[r], src4 + r, 16);
        }
        __pipeline_commit();
        __pipeline_wait_prior(0);
        __syncthreads();

        const float aw = __ldg(anc13 + 2 * a + 0);
        const float ah = __ldg(anc13 + 2 * a + 1);

        #pragma unroll
        for (int k = 0; k < 2; ++k) {
            const int lc = t + k * TPB;
            if (k == 1 && lc >= 169) break;

            const float* sc = s + m + lc;

            const float o0 = sc[0 * 169];
            const float o1 = sc[1 * 169];
            const float o2 = sc[2 * 169];
            const float o3 = sc[3 * 169];
            const float o4 = sc[4 * 169];

            float best = sc[5 * 169];
            int bi = 0;
            #pragma unroll
            for (int c = 1; c < 10; ++c) {
                const float q = sc[(5 + c) * 169];
                if (q > best) { best = q; bi = c; }
            }

            const int h = lc / 13;
            const int w = lc - h * 13;

            const float px = ((float)w + o1) * 32.0f;
            const float py = ((float)h + o2) * 32.0f;
            const float pw = aw * __expf(o3);
            const float ph = ah * __expf(o4);

            const size_t orow = (size_t)ROWBASE13 + ((size_t)b * 169 + lc) * 3 + a;
            float2* ob = (float2*)(boxes + orow * 6);
            ob[0] = make_float2(o0,              px - 0.5f * pw);
            ob[1] = make_float2(py - 0.5f * ph,  px + 0.5f * pw);
            ob[2] = make_float2(py + 0.5f * ph,  (float)bi);

            mask[orow] = (o0 > thr) ? 1.0f : 0.0f;
        }
    }
}

// ---- host: tensormap via runtime-queried driver entry point (no -lcuda) ----
typedef CUresult (*PFN_encode_t)(
    CUtensorMap*, CUtensorMapDataType, cuuint32_t, void*,
    const cuuint64_t*, const cuuint64_t*, const cuuint32_t*, const cuuint32_t*,
    CUtensorMapInterleave, CUtensorMapSwizzle, CUtensorMapL2promotion,
    CUtensorMapFloatOOBfill);

static PFN_encode_t get_encoder()
{
    static PFN_encode_t fn = nullptr;
    if (!fn) {
        void* p = nullptr;
#if CUDART_VERSION >= 12050
        cudaDriverEntryPointQueryResult qr;
        cudaGetDriverEntryPointByVersion("cuTensorMapEncodeTiled", &p, 12000,
                                         cudaEnableDefault, &qr);
#else
        cudaGetDriverEntryPoint("cuTensorMapEncodeTiled", &p, cudaEnableDefault);
#endif
        fn = (PFN_encode_t)p;
    }
    return fn;
}

static void make_map(CUtensorMap* m, const void* ptr, uint64_t hw, uint32_t boxw)
{
    cuuint64_t dims[2]    = { hw, (cuuint64_t)(NCH * 128) };
    cuuint64_t strides[1] = { hw * 4 };           // bytes; 16B multiple
    cuuint32_t box[2]     = { boxw, NCH };
    cuuint32_t estr[2]    = { 1, 1 };
    get_encoder()(m, CU_TENSOR_MAP_DATA_TYPE_FLOAT32, 2, const_cast<void*>(ptr),
                  dims, strides, box, estr,
                  CU_TENSOR_MAP_INTERLEAVE_NONE, CU_TENSOR_MAP_SWIZZLE_NONE,
                  CU_TENSOR_MAP_L2_PROMOTION_L2_128B,
                  CU_TENSOR_MAP_FLOAT_OOB_FILL_NONE);
}

extern "C" void kernel_launch(void* const* d_in, const int* in_sizes, int n_in,
                              void* d_out, int out_size)
{
    const float* out13 = (const float*)d_in[0];
    const float* out26 = (const float*)d_in[1];
    const float* out52 = (const float*)d_in[2];
    const float* anc13 = (const float*)d_in[3];
    const float* anc26 = (const float*)d_in[4];
    const float* anc52 = (const float*)d_in[5];
    const float* thr   = (const float*)d_in[6];

    float* out = (float*)d_out;
    const int rowsTot = ROWS13 + ROWS26 + ROWS52;   // 1,362,816

    float* boxes = out;                       // [rowsTot, 6]
    float* mask  = out + (size_t)rowsTot * 6; // [rowsTot]

    CUtensorMap map26, map52;
    make_map(&map26, out26, 676,  T26);
    make_map(&map52, out52, 2704, T52);

    decode_fused_kernel<<<B52T + B26T + B13, TPB>>>(
        out13, anc13, anc26, anc52, thr, boxes, mask, map26, map52);
}